// round 3
// baseline (speedup 1.0000x reference)
#include <cuda_runtime.h>
#include <cstdint>

// Output layout:
//   [0,       N*D)      mean_messages (float)
//   [N*D,     N*D+N)    last_timestamps (float)
//   [N*D+N,   N*D+2N)   counts (float)
//
// counting-sort events by node id (hist -> lookback scan -> bin), then one
// warp per node gathers its rows, sums in registers, and writes mean, count,
// and last-timestamp (from the max event index in its bin).

#define MAX_B   (1 << 21)   // up to 2M events
#define MAX_N   (1 << 18)   // up to 256k nodes
#define SCAN_BLK 1024
#define MAX_NB  ((MAX_N + SCAN_BLK - 1) / SCAN_BLK)

__device__ int          g_hist[MAX_N];
__device__ int          g_off[MAX_N];
__device__ int          g_cur[MAX_N];
__device__ int          g_order[MAX_B];
__device__ unsigned int g_state[MAX_NB];   // [31:30]=flag (1=agg,2=prefix), [29:0]=value

// ---------------- histogram (int4 vectorized) ----------------
__global__ void hist_kernel(const int4* __restrict__ ids4, int B4,
                            const int* __restrict__ ids, int B) {
    int i = blockIdx.x * blockDim.x + threadIdx.x;
    if (i < B4) {
        int4 v = ids4[i];
        atomicAdd(&g_hist[v.x], 1);
        atomicAdd(&g_hist[v.y], 1);
        atomicAdd(&g_hist[v.z], 1);
        atomicAdd(&g_hist[v.w], 1);
    }
    // tail (B % 4 elements) handled by the first threads of block 0
    if (blockIdx.x == 0 && threadIdx.x < (B - B4 * 4)) {
        atomicAdd(&g_hist[ids[B4 * 4 + threadIdx.x]], 1);
    }
}

// ---------------- block exclusive scan ----------------
__device__ __forceinline__ int block_excl_scan(int v, int tid, int* total) {
    int lane = tid & 31, wid = tid >> 5;
    int inc = v;
    #pragma unroll
    for (int d = 1; d < 32; d <<= 1) {
        int t = __shfl_up_sync(0xffffffffu, inc, d);
        if (lane >= d) inc += t;
    }
    __shared__ int wsum[32];
    if (lane == 31) wsum[wid] = inc;
    __syncthreads();
    if (wid == 0) {
        int w = wsum[lane];
        #pragma unroll
        for (int d = 1; d < 32; d <<= 1) {
            int t = __shfl_up_sync(0xffffffffu, w, d);
            if (lane >= d) w += t;
        }
        wsum[lane] = w;
    }
    __syncthreads();
    int excl = inc - v + (wid > 0 ? wsum[wid - 1] : 0);
    if (total) *total = wsum[31];
    return excl;
}

// ---------------- single-pass decoupled-lookback scan ----------------
__global__ void scan_kernel(int N) {
    int tid = threadIdx.x;
    int bid = blockIdx.x;
    int i = bid * SCAN_BLK + tid;
    int v = (i < N) ? g_hist[i] : 0;
    int tot;
    int excl = block_excl_scan(v, tid, &tot);

    __shared__ int s_prev;
    if (tid == 0) {
        // publish block aggregate
        atomicExch(&g_state[bid], (1u << 30) | (unsigned)tot);
        // look back over predecessors
        int prev = 0;
        for (int j = bid - 1; j >= 0; ) {
            unsigned s;
            do { s = atomicAdd(&g_state[j], 0u); } while ((s >> 30) == 0u);
            prev += (int)(s & 0x3FFFFFFFu);
            if ((s >> 30) == 2u) break;
            j--;
        }
        // publish inclusive prefix
        atomicExch(&g_state[bid], (2u << 30) | (unsigned)(prev + tot));
        s_prev = prev;
    }
    __syncthreads();
    int o = s_prev + excl;
    if (i < N) { g_off[i] = o; g_cur[i] = o; }
}

// ---------------- binning (int4 vectorized) ----------------
__global__ void bin_kernel(const int4* __restrict__ ids4, int B4,
                           const int* __restrict__ ids, int B) {
    int i = blockIdx.x * blockDim.x + threadIdx.x;
    if (i < B4) {
        int4 v = ids4[i];
        int e = i * 4;
        g_order[atomicAdd(&g_cur[v.x], 1)] = e;
        g_order[atomicAdd(&g_cur[v.y], 1)] = e + 1;
        g_order[atomicAdd(&g_cur[v.z], 1)] = e + 2;
        g_order[atomicAdd(&g_cur[v.w], 1)] = e + 3;
    }
    if (blockIdx.x == 0 && threadIdx.x < (B - B4 * 4)) {
        int e = B4 * 4 + threadIdx.x;
        g_order[atomicAdd(&g_cur[ids[e]], 1)] = e;
    }
}

// ---------------- gather-sum: one warp per node ----------------
__global__ void sum_kernel(const float4* __restrict__ messages4, // [B, Dq]
                           const float* __restrict__ ts,         // [B]
                           float4* __restrict__ sums4,           // [N, Dq]
                           float* __restrict__ last_ts,          // [N]
                           float* __restrict__ counts,           // [N]
                           int N, int Dq /* = D/4 = 64 */) {
    int warp = blockIdx.x * (blockDim.x >> 5) + (threadIdx.x >> 5);
    int lane = threadIdx.x & 31;
    if (warp >= N) return;
    int n = warp;

    int c = g_hist[n];
    int start = g_off[n];

    float4 a0 = make_float4(0.f, 0.f, 0.f, 0.f);
    float4 a1 = make_float4(0.f, 0.f, 0.f, 0.f);
    int emax = -1;

    for (int base = 0; base < c; base += 32) {
        int m = min(32, c - base);
        int idx = (lane < m) ? __ldg(&g_order[start + base + lane]) : -1;
        emax = max(emax, idx);
        for (int k = 0; k < m; k++) {
            int e = __shfl_sync(0xffffffffu, idx, k);
            const float4* row = messages4 + (long long)e * Dq;
            float4 r0 = __ldg(&row[lane]);
            float4 r1 = __ldg(&row[lane + 32]);
            a0.x += r0.x; a0.y += r0.y; a0.z += r0.z; a0.w += r0.w;
            a1.x += r1.x; a1.y += r1.y; a1.z += r1.z; a1.w += r1.w;
        }
    }

    // warp max of event index
    #pragma unroll
    for (int d = 16; d > 0; d >>= 1)
        emax = max(emax, __shfl_xor_sync(0xffffffffu, emax, d));

    float inv = 1.0f / fmaxf((float)c, 1.0f);
    a0.x *= inv; a0.y *= inv; a0.z *= inv; a0.w *= inv;
    a1.x *= inv; a1.y *= inv; a1.z *= inv; a1.w *= inv;

    float4* dst = sums4 + (long long)n * Dq;
    dst[lane]      = a0;
    dst[lane + 32] = a1;
    if (lane == 0) {
        counts[n]  = (float)c;
        last_ts[n] = (c > 0) ? __ldg(&ts[emax]) : 0.0f;
    }
}

extern "C" void kernel_launch(void* const* d_in, const int* in_sizes, int n_in,
                              void* d_out, int out_size) {
    const int*   node_ids   = (const int*)  d_in[0];
    const float* messages   = (const float*)d_in[1];
    const float* timestamps = (const float*)d_in[2];

    const int B  = in_sizes[0];
    const int D  = in_sizes[1] / B;            // 256
    const int N  = out_size / (D + 2);         // 100000
    const int Dq = D / 4;                      // 64
    const int B4 = B / 4;
    const int NB = (N + SCAN_BLK - 1) / SCAN_BLK;

    float* out     = (float*)d_out;
    float* sums    = out;                      // [N, D]
    float* last_ts = out + (long long)N * D;   // [N]
    float* counts  = last_ts + N;              // [N]

    void* hist_ptr  = nullptr;
    void* state_ptr = nullptr;
    cudaGetSymbolAddress(&hist_ptr,  g_hist);
    cudaGetSymbolAddress(&state_ptr, g_state);

    // 1-2. zero histogram + scan state (graph memset nodes)
    cudaMemsetAsync(hist_ptr,  0, (size_t)N  * sizeof(int), 0);
    cudaMemsetAsync(state_ptr, 0, (size_t)NB * sizeof(unsigned int), 0);

    // 3. histogram
    hist_kernel<<<(B4 + 255) / 256, 256>>>((const int4*)node_ids, B4, node_ids, B);

    // 4. exclusive scan -> offsets + cursors (single pass, decoupled lookback)
    scan_kernel<<<NB, SCAN_BLK>>>(N);

    // 5. bin event indices
    bin_kernel<<<(B4 + 255) / 256, 256>>>((const int4*)node_ids, B4, node_ids, B);

    // 6. gather + mean + count + last-ts, one warp per node
    {
        int thr = 256;
        int warps_per_blk = thr / 32;
        int blocks = (N + warps_per_blk - 1) / warps_per_blk;
        sum_kernel<<<blocks, thr>>>((const float4*)messages, timestamps,
                                    (float4*)sums, last_ts, counts, N, Dq);
    }
}

// round 4
// speedup vs baseline: 1.1168x; 1.1168x over previous
#include <cuda_runtime.h>
#include <cstdint>

// Output layout:
//   [0,       N*D)      mean_messages (float)
//   [N*D,     N*D+N)    last_timestamps (float)
//   [N*D+N,   N*D+2N)   counts (float)

#define MAX_B   (1 << 21)
#define MAX_N   (1 << 18)
#define SCAN_BLK 1024
#define MAX_NB  ((MAX_N + SCAN_BLK - 1) / SCAN_BLK)

__device__ int          g_hist[MAX_N];
__device__ int          g_off[MAX_N];
__device__ int          g_cur[MAX_N];
__device__ int          g_order[MAX_B];
__device__ unsigned int g_state[MAX_NB];   // [31:30]=flag, [29:0]=value

// ---------------- histogram (also zeroes lookback state for the scan) ------
__global__ void hist_kernel(const int4* __restrict__ ids4, int B4,
                            const int* __restrict__ ids, int B, int NB) {
    int i = blockIdx.x * blockDim.x + threadIdx.x;
    if (i < NB) g_state[i] = 0u;     // scan runs strictly after this kernel
    if (i < B4) {
        int4 v = ids4[i];
        atomicAdd(&g_hist[v.x], 1);
        atomicAdd(&g_hist[v.y], 1);
        atomicAdd(&g_hist[v.z], 1);
        atomicAdd(&g_hist[v.w], 1);
    }
    if (blockIdx.x == 0 && threadIdx.x < (B - B4 * 4)) {
        atomicAdd(&g_hist[ids[B4 * 4 + threadIdx.x]], 1);
    }
}

// ---------------- block exclusive scan ----------------
__device__ __forceinline__ int block_excl_scan(int v, int tid, int* total) {
    int lane = tid & 31, wid = tid >> 5;
    int inc = v;
    #pragma unroll
    for (int d = 1; d < 32; d <<= 1) {
        int t = __shfl_up_sync(0xffffffffu, inc, d);
        if (lane >= d) inc += t;
    }
    __shared__ int wsum[32];
    if (lane == 31) wsum[wid] = inc;
    __syncthreads();
    if (wid == 0) {
        int w = wsum[lane];
        #pragma unroll
        for (int d = 1; d < 32; d <<= 1) {
            int t = __shfl_up_sync(0xffffffffu, w, d);
            if (lane >= d) w += t;
        }
        wsum[lane] = w;
    }
    __syncthreads();
    int excl = inc - v + (wid > 0 ? wsum[wid - 1] : 0);
    if (total) *total = wsum[31];
    return excl;
}

// ---------------- single-pass decoupled-lookback scan ----------------
__global__ void scan_kernel(int N) {
    int tid = threadIdx.x;
    int bid = blockIdx.x;
    int i = bid * SCAN_BLK + tid;
    int v = (i < N) ? g_hist[i] : 0;
    int tot;
    int excl = block_excl_scan(v, tid, &tot);

    __shared__ int s_prev;
    if (tid == 0) {
        atomicExch(&g_state[bid], (1u << 30) | (unsigned)tot);
        int prev = 0;
        for (int j = bid - 1; j >= 0; ) {
            unsigned s;
            do { s = atomicAdd(&g_state[j], 0u); } while ((s >> 30) == 0u);
            prev += (int)(s & 0x3FFFFFFFu);
            if ((s >> 30) == 2u) break;
            j--;
        }
        atomicExch(&g_state[bid], (2u << 30) | (unsigned)(prev + tot));
        s_prev = prev;
    }
    __syncthreads();
    int o = s_prev + excl;
    if (i < N) { g_off[i] = o; g_cur[i] = o; }
}

// ---------------- binning ----------------
__global__ void bin_kernel(const int4* __restrict__ ids4, int B4,
                           const int* __restrict__ ids, int B) {
    int i = blockIdx.x * blockDim.x + threadIdx.x;
    if (i < B4) {
        int4 v = ids4[i];
        int e = i * 4;
        g_order[atomicAdd(&g_cur[v.x], 1)] = e;
        g_order[atomicAdd(&g_cur[v.y], 1)] = e + 1;
        g_order[atomicAdd(&g_cur[v.z], 1)] = e + 2;
        g_order[atomicAdd(&g_cur[v.w], 1)] = e + 3;
    }
    if (blockIdx.x == 0 && threadIdx.x < (B - B4 * 4)) {
        int e = B4 * 4 + threadIdx.x;
        g_order[atomicAdd(&g_cur[ids[e]], 1)] = e;
    }
}

// ---------------- gather-sum: one warp per node, 2-event unroll ------------
__global__ void __launch_bounds__(256, 6)
sum_kernel(const float4* __restrict__ messages4, // [B, Dq]
           const float* __restrict__ ts,         // [B]
           float4* __restrict__ sums4,           // [N, Dq]
           float* __restrict__ last_ts,          // [N]
           float* __restrict__ counts,           // [N]
           int N, int Dq /* = D/4 = 64 */) {
    int warp = blockIdx.x * (blockDim.x >> 5) + (threadIdx.x >> 5);
    int lane = threadIdx.x & 31;
    if (warp >= N) return;
    int n = warp;

    int c = g_hist[n];
    int start = g_off[n];

    float4 a0 = make_float4(0.f, 0.f, 0.f, 0.f);
    float4 a1 = make_float4(0.f, 0.f, 0.f, 0.f);
    int emax = -1;

    for (int base = 0; base < c; base += 32) {
        int m = min(32, c - base);
        int idx = (lane < m) ? __ldg(&g_order[start + base + lane]) : -1;
        emax = max(emax, idx);

        int k = 0;
        for (; k + 2 <= m; k += 2) {
            int e0 = __shfl_sync(0xffffffffu, idx, k);
            int e1 = __shfl_sync(0xffffffffu, idx, k + 1);
            const float4* row0 = messages4 + (long long)e0 * Dq;
            const float4* row1 = messages4 + (long long)e1 * Dq;
            float4 r00 = __ldg(&row0[lane]);
            float4 r01 = __ldg(&row0[lane + 32]);
            float4 r10 = __ldg(&row1[lane]);
            float4 r11 = __ldg(&row1[lane + 32]);
            a0.x += r00.x; a0.y += r00.y; a0.z += r00.z; a0.w += r00.w;
            a1.x += r01.x; a1.y += r01.y; a1.z += r01.z; a1.w += r01.w;
            a0.x += r10.x; a0.y += r10.y; a0.z += r10.z; a0.w += r10.w;
            a1.x += r11.x; a1.y += r11.y; a1.z += r11.z; a1.w += r11.w;
        }
        if (k < m) {
            int e0 = __shfl_sync(0xffffffffu, idx, k);
            const float4* row0 = messages4 + (long long)e0 * Dq;
            float4 r00 = __ldg(&row0[lane]);
            float4 r01 = __ldg(&row0[lane + 32]);
            a0.x += r00.x; a0.y += r00.y; a0.z += r00.z; a0.w += r00.w;
            a1.x += r01.x; a1.y += r01.y; a1.z += r01.z; a1.w += r01.w;
        }
    }

    #pragma unroll
    for (int d = 16; d > 0; d >>= 1)
        emax = max(emax, __shfl_xor_sync(0xffffffffu, emax, d));

    float inv = 1.0f / fmaxf((float)c, 1.0f);
    a0.x *= inv; a0.y *= inv; a0.z *= inv; a0.w *= inv;
    a1.x *= inv; a1.y *= inv; a1.z *= inv; a1.w *= inv;

    float4* dst = sums4 + (long long)n * Dq;
    dst[lane]      = a0;
    dst[lane + 32] = a1;
    if (lane == 0) {
        counts[n]  = (float)c;
        last_ts[n] = (c > 0) ? __ldg(&ts[emax]) : 0.0f;
    }
}

extern "C" void kernel_launch(void* const* d_in, const int* in_sizes, int n_in,
                              void* d_out, int out_size) {
    const int*   node_ids   = (const int*)  d_in[0];
    const float* messages   = (const float*)d_in[1];
    const float* timestamps = (const float*)d_in[2];

    const int B  = in_sizes[0];
    const int D  = in_sizes[1] / B;            // 256
    const int N  = out_size / (D + 2);         // 100000
    const int Dq = D / 4;                      // 64
    const int B4 = B / 4;
    const int NB = (N + SCAN_BLK - 1) / SCAN_BLK;

    float* out     = (float*)d_out;
    float* sums    = out;                      // [N, D]
    float* last_ts = out + (long long)N * D;   // [N]
    float* counts  = last_ts + N;              // [N]

    void* hist_ptr = nullptr;
    cudaGetSymbolAddress(&hist_ptr, g_hist);

    // 1. zero histogram (graph memset node)
    cudaMemsetAsync(hist_ptr, 0, (size_t)N * sizeof(int), 0);

    // 2. histogram (+ zero lookback state)
    hist_kernel<<<(B4 + 255) / 256, 256>>>((const int4*)node_ids, B4,
                                           node_ids, B, NB);

    // 3. exclusive scan -> offsets + cursors
    scan_kernel<<<NB, SCAN_BLK>>>(N);

    // 4. bin event indices
    bin_kernel<<<(B4 + 255) / 256, 256>>>((const int4*)node_ids, B4, node_ids, B);

    // 5. gather + mean + count + last-ts
    {
        int thr = 256;
        int warps_per_blk = thr / 32;
        int blocks = (N + warps_per_blk - 1) / warps_per_blk;
        sum_kernel<<<blocks, thr>>>((const float4*)messages, timestamps,
                                    (float4*)sums, last_ts, counts, N, Dq);
    }
}